// round 14
// baseline (speedup 1.0000x reference)
#include <cuda_runtime.h>
#include <cuda_fp16.h>

#define N_USERS 50000
#define NN      100000        // total nodes
#define EMBED   64
#define FDIM    192           // 3 streams interleaved: [e | img | txt]
#define NEDGES  1600000
#define BATCH   4096
#define CAT_RATE 0.02f

// ---------------- device scratch ----------------------------------------------
__device__ __half g_F0[NN * FDIM];
__device__ __half g_F1[NN * FDIM];
__device__ __half g_F2[NN * FDIM];
__device__ int           g_count[NN];       // zero at load; re-zeroed each launch
__device__ int           g_rowstart[NN + 1];
__device__ unsigned char g_rank8[NEDGES];   // within-row rank (max deg << 256)
__device__ int           g_needflag[NN];    // rows needing F2; re-zeroed each launch
__device__ int2          g_edge[NEDGES];    // (col, val-as-int-bits), row-grouped
__device__ int           g_blocksums[256];

// ---------------- pure hist (+packed rank), 8 edges/thread ---------------------
#define NB_HIST ((NEDGES / 8 + 255) / 256)      // 782

__global__ void k_hist(const int* __restrict__ rows) {
    int e8 = (blockIdx.x * blockDim.x + threadIdx.x) * 8;
    if (e8 < NEDGES) {
        int4 ra = *(const int4*)(rows + e8);
        int4 rb = *(const int4*)(rows + e8 + 4);
        unsigned int k0 = atomicAdd(&g_count[ra.x], 1);
        unsigned int k1 = atomicAdd(&g_count[ra.y], 1);
        unsigned int k2 = atomicAdd(&g_count[ra.z], 1);
        unsigned int k3 = atomicAdd(&g_count[ra.w], 1);
        unsigned int k4 = atomicAdd(&g_count[rb.x], 1);
        unsigned int k5 = atomicAdd(&g_count[rb.y], 1);
        unsigned int k6 = atomicAdd(&g_count[rb.z], 1);
        unsigned int k7 = atomicAdd(&g_count[rb.w], 1);
        uint2 packed;
        packed.x = (k0 & 0xFF) | ((k1 & 0xFF) << 8) | ((k2 & 0xFF) << 16) | ((k3 & 0xFF) << 24);
        packed.y = (k4 & 0xFF) | ((k5 & 0xFF) << 8) | ((k6 & 0xFF) << 16) | ((k7 & 0xFF) << 24);
        *(uint2*)(g_rank8 + e8) = packed;
    }
}

// ---------------- scan (NN elements), two-pass ---------------------------------
#define SCAN_T 512
#define SCAN_NB ((NN + SCAN_T - 1) / SCAN_T)   // 196

__global__ void k_scan_p1() {
    __shared__ int sm[SCAN_T];
    int i = blockIdx.x * SCAN_T + threadIdx.x;
    sm[threadIdx.x] = (i < NN) ? g_count[i] : 0;
    __syncthreads();
    for (int off = SCAN_T / 2; off > 0; off >>= 1) {
        if (threadIdx.x < off) sm[threadIdx.x] += sm[threadIdx.x + off];
        __syncthreads();
    }
    if (threadIdx.x == 0) g_blocksums[blockIdx.x] = sm[0];
}

__global__ void k_scan_p3() {
    __shared__ int sm[SCAN_T];
    __shared__ int s_off;
    int contrib = (threadIdx.x < blockIdx.x) ? g_blocksums[threadIdx.x] : 0;
    sm[threadIdx.x] = contrib;
    __syncthreads();
    for (int off = SCAN_T / 2; off > 0; off >>= 1) {
        if (threadIdx.x < off) sm[threadIdx.x] += sm[threadIdx.x + off];
        __syncthreads();
    }
    if (threadIdx.x == 0) s_off = sm[0];
    __syncthreads();
    int i = blockIdx.x * SCAN_T + threadIdx.x;
    int v = (i < NN) ? g_count[i] : 0;
    sm[threadIdx.x] = v;
    __syncthreads();
    for (int off = 1; off < SCAN_T; off <<= 1) {
        int add = (threadIdx.x >= off) ? sm[threadIdx.x - off] : 0;
        __syncthreads();
        sm[threadIdx.x] += add;
        __syncthreads();
    }
    int excl = sm[threadIdx.x] - v + s_off;
    if (i < NN) g_rowstart[i] = excl;
    if (i == 0) g_rowstart[NN] = NEDGES;
}

// ---------------- fused: scatter (4 edges/thread) + feature init, 1:9 stripe ---
#define NB_SCAT  ((NEDGES / 4 + 255) / 256)      // 1563
#define NB_INITE ((NN * EMBED / 4 + 255) / 256)  // 6250
#define NB_TILES (NN / 32)                       // 3125
#define NB_INIT  (NB_INITE + 2 * NB_TILES)       // 12500
#define SI_GRID  (NB_SCAT * 9)                   // 14067: g%9==0 -> scatter

__global__ void k_scatter_init(const int* __restrict__ rows, const int* __restrict__ cols,
                               const float* __restrict__ vals,
                               const float* __restrict__ E0,
                               const float* __restrict__ Wimg,
                               const float* __restrict__ Wtxt) {
    __shared__ float sm[64][33];
    int g = blockIdx.x;
    if (g % 9 == 0) {
        int sb = g / 9;
        int e4 = (sb * 256 + threadIdx.x) * 4;
        if (e4 < NEDGES) {
            int4   r4 = *(const int4*)(rows + e4);
            int4   c4 = *(const int4*)(cols + e4);
            float4 v4 = *(const float4*)(vals + e4);
            unsigned int kk = *(const unsigned int*)(g_rank8 + e4);
            g_edge[g_rowstart[r4.x] + ( kk        & 0xFF)] = make_int2(c4.x, __float_as_int(v4.x));
            g_edge[g_rowstart[r4.y] + ((kk >>  8) & 0xFF)] = make_int2(c4.y, __float_as_int(v4.y));
            g_edge[g_rowstart[r4.z] + ((kk >> 16) & 0xFF)] = make_int2(c4.z, __float_as_int(v4.z));
            g_edge[g_rowstart[r4.w] + ((kk >> 24) & 0xFF)] = make_int2(c4.w, __float_as_int(v4.w));
        }
        return;
    }
    int b = g - (g / 9) - 1;
    if (b >= NB_INIT) return;
    if (b < NB_INITE) {
        int i = b * 256 + threadIdx.x;
        if (i < NN * (EMBED / 4)) {
            int n  = i >> 4;
            int d4 = (i & 15) * 4;
            float4 v = ((const float4*)E0)[i];
            __half2* dst = (__half2*)(g_F0 + (size_t)n * FDIM + d4);
            dst[0] = __floats2half2_rn(v.x, v.y);
            dst[1] = __floats2half2_rn(v.z, v.w);
        }
        return;
    }
    b -= NB_INITE;
    const float* W = (b < NB_TILES) ? Wimg : Wtxt;
    int plane_off  = (b < NB_TILES) ? 64 : 128;
    int tile = (b < NB_TILES) ? b : (b - NB_TILES);
    int n0 = tile * 32;
    int tx = threadIdx.x & 31;
    int ty = threadIdx.x >> 5;
    #pragma unroll
    for (int k = 0; k < 8; k++) {
        int d = k * 8 + ty;
        sm[d][tx] = W[(size_t)d * NN + n0 + tx];
    }
    __syncthreads();
    #pragma unroll
    for (int k = 0; k < 4; k++) {
        int row = k * 8 + ty;
        int n = n0 + row;
        #pragma unroll
        for (int dk = 0; dk < 2; dk++) {
            int d = dk * 32 + tx;
            g_F0[(size_t)n * FDIM + plane_off + d] = __float2half_rn(sm[d][row]);
        }
    }
}

// ---------------- edge accumulation helper (LDG.128 mapping) --------------------
// lane < 24 owns 16 B = 8 dims of one plane (plane = lane>>3, dims = (lane&7)*8..+8)
__device__ __forceinline__ void acc_edge(float* acc, float v, int4 h) {
    float2 f;
    f = __half22float2(*(__half2*)&h.x); acc[0] += v * f.x; acc[1] += v * f.y;
    f = __half22float2(*(__half2*)&h.y); acc[2] += v * f.x; acc[3] += v * f.y;
    f = __half22float2(*(__half2*)&h.z); acc[4] += v * f.x; acc[5] += v * f.y;
    f = __half22float2(*(__half2*)&h.w); acc[6] += v * f.x; acc[7] += v * f.y;
}

__device__ __forceinline__ void gather_row(float* acc, int s, int e, int ll,
                                           const __half* __restrict__ A) {
    int k = s;
    if ((k & 1) && k < e) {          // parity prologue -> int4 edge loads aligned
        int2 ed = __ldg(&g_edge[k]);
        int4 h = __ldg((const int4*)(A + (size_t)ed.x * FDIM) + ll);
        acc_edge(acc, __int_as_float(ed.y), h);
        k++;
    }
    for (; k + 1 < e; k += 2) {
        int4 ee = __ldg((const int4*)g_edge + (k >> 1));   // 2 edges in one LDG.128
        int4 hA = __ldg((const int4*)(A + (size_t)ee.x * FDIM) + ll);
        int4 hB = __ldg((const int4*)(A + (size_t)ee.z * FDIM) + ll);
        acc_edge(acc, __int_as_float(ee.y), hA);
        acc_edge(acc, __int_as_float(ee.w), hB);
    }
    if (k < e) {
        int2 ed = __ldg(&g_edge[k]);
        int4 h = __ldg((const int4*)(A + (size_t)ed.x * FDIM) + ll);
        acc_edge(acc, __int_as_float(ed.y), h);
    }
}

// ---------------- SPMM row body (LDG.128 gathers, fp32 accum) -------------------
__device__ __forceinline__ void spmm_row(int row, int lane,
                                         const __half* __restrict__ A, __half* __restrict__ B,
                                         const float* __restrict__ bias_i,
                                         const float* __restrict__ bias_t) {
    int s = g_rowstart[row];
    int e = g_rowstart[row + 1];
    int ll = (lane < 24) ? lane : 0;
    float acc[8] = {0.f, 0.f, 0.f, 0.f, 0.f, 0.f, 0.f, 0.f};
    gather_row(acc, s, e, ll, A);

    int plane = lane >> 3, sub = lane & 7;
    if (plane == 1 || plane == 2) {
        const float* bp = (plane == 1) ? bias_i : bias_t;
        float4 b0 = *(const float4*)(bp + sub * 8);
        float4 b1 = *(const float4*)(bp + sub * 8 + 4);
        acc[0] += b0.x; acc[1] += b0.y; acc[2] += b0.z; acc[3] += b0.w;
        acc[4] += b1.x; acc[5] += b1.y; acc[6] += b1.z; acc[7] += b1.w;
    }
    if (lane < 24) {
        int4 o;
        *(__half2*)&o.x = __floats2half2_rn(acc[0], acc[1]);
        *(__half2*)&o.y = __floats2half2_rn(acc[2], acc[3]);
        *(__half2*)&o.z = __floats2half2_rn(acc[4], acc[5]);
        *(__half2*)&o.w = __floats2half2_rn(acc[6], acc[7]);
        *((int4*)(B + (size_t)row * FDIM) + lane) = o;
    }
}

// ---------------- SPMM1 (dense) + need-marker trailing blocks -------------------
#define SPMM_BLOCKS ((NN * 32 + 255) / 256)     // 12500
#define MARK_BLOCKS ((3 * BATCH) / 8)           // 1536 (one warp per target row)

__global__ void k_spmm_mark(const __half* __restrict__ A, __half* __restrict__ B,
                            const float* __restrict__ bias_i, const float* __restrict__ bias_t,
                            const int* __restrict__ uidx, const int* __restrict__ pidx,
                            const int* __restrict__ nidx) {
    int lane = threadIdx.x & 31;
    if (blockIdx.x >= SPMM_BLOCKS) {
        int warp = ((blockIdx.x - SPMM_BLOCKS) * blockDim.x + threadIdx.x) >> 5;
        int g = warp / BATCH;
        int i = warp - g * BATCH;
        int idx = (g == 0) ? __ldg(&uidx[i]) : (g == 1) ? __ldg(&pidx[i]) : __ldg(&nidx[i]);
        int row = (g == 0) ? idx : (N_USERS + idx);
        if (lane == 0) g_needflag[row] = 1;
        int s = g_rowstart[row];
        int e = g_rowstart[row + 1];
        for (int k = s + lane; k < e; k += 32)
            g_needflag[g_edge[k].x] = 1;
        return;
    }
    int warp = (blockIdx.x * blockDim.x + threadIdx.x) >> 5;
    if (warp >= NN) return;
    spmm_row(warp, lane, A, B, bias_i, bias_t);
}

// ---------------- SPMM2 (filtered by needflag) ---------------------------------
__global__ void k_spmm_filt(const __half* __restrict__ A, __half* __restrict__ B,
                            const float* __restrict__ bias_i, const float* __restrict__ bias_t) {
    int warp = (blockIdx.x * blockDim.x + threadIdx.x) >> 5;
    int lane = threadIdx.x & 31;
    if (warp >= NN) return;
    if (g_needflag[warp] == 0) return;
    spmm_row(warp, lane, A, B, bias_i, bias_t);
}

// ---------------- final: on-the-fly layer-3 + sum + mean + l2 + gathers -------
#define FIN_BLOCKS ((3 * BATCH * 32 + 255) / 256)          // 1536
#define ZERO_N     (2 * NN)                                // count + needflag
#define ZERO_BLOCKS ((ZERO_N + 255) / 256)                 // 782

__global__ void k_final(const int* __restrict__ uidx, const int* __restrict__ pidx,
                        const int* __restrict__ nidx,
                        const float* __restrict__ bias_i, const float* __restrict__ bias_t,
                        float* __restrict__ out) {
    if (blockIdx.x >= FIN_BLOCKS) {
        int i = (blockIdx.x - FIN_BLOCKS) * 256 + threadIdx.x;
        if (i < NN) g_count[i] = 0;
        else if (i < 2 * NN) g_needflag[i - NN] = 0;
        return;
    }
    int warp = (blockIdx.x * blockDim.x + threadIdx.x) >> 5;
    int lane = threadIdx.x & 31;
    int g = warp / BATCH;
    int i = warp - g * BATCH;
    int idx = (g == 0) ? __ldg(&uidx[i]) : (g == 1) ? __ldg(&pidx[i]) : __ldg(&nidx[i]);
    int row = (g == 0) ? idx : (N_USERS + idx);

    int ll = (lane < 24) ? lane : 0;
    int plane = lane >> 3, sub = lane & 7;

    // hoisted stored-layer row loads (3 x LDG.128)
    int4 h0 = __ldg((const int4*)(g_F0 + (size_t)row * FDIM) + ll);
    int4 h1 = __ldg((const int4*)(g_F1 + (size_t)row * FDIM) + ll);
    int4 h2 = __ldg((const int4*)(g_F2 + (size_t)row * FDIM) + ll);

    // layer-3 propagation on the fly from F2 (fp32 accum)
    float acc[8] = {0.f, 0.f, 0.f, 0.f, 0.f, 0.f, 0.f, 0.f};
    gather_row(acc, g_rowstart[row], g_rowstart[row + 1], ll, g_F2);

    if (plane == 1 || plane == 2) {
        const float* bp = (plane == 1) ? bias_i : bias_t;
        float4 b0 = *(const float4*)(bp + sub * 8);
        float4 b1 = *(const float4*)(bp + sub * 8 + 4);
        acc[0] += b0.x; acc[1] += b0.y; acc[2] += b0.z; acc[3] += b0.w;
        acc[4] += b1.x; acc[5] += b1.y; acc[6] += b1.z; acc[7] += b1.w;
    }

    // mean over 4 layers
    float m[8];
    {
        const __half2* q0 = (const __half2*)&h0;
        const __half2* q1 = (const __half2*)&h1;
        const __half2* q2 = (const __half2*)&h2;
        #pragma unroll
        for (int j = 0; j < 4; j++) {
            float2 f0 = __half22float2(q0[j]);
            float2 f1 = __half22float2(q1[j]);
            float2 f2 = __half22float2(q2[j]);
            m[2 * j]     = (f0.x + f1.x + f2.x + acc[2 * j])     * 0.25f;
            m[2 * j + 1] = (f0.y + f1.y + f2.y + acc[2 * j + 1]) * 0.25f;
        }
    }

    // plane norms -> warp-reduced
    float sq = 0.f;
    #pragma unroll
    for (int j = 0; j < 8; j++) sq += m[j] * m[j];
    float ci = (plane == 1) ? sq : 0.f;
    float ct = (plane == 2) ? sq : 0.f;
    #pragma unroll
    for (int off = 16; off > 0; off >>= 1) {
        ci += __shfl_xor_sync(0xFFFFFFFFu, ci, off);
        ct += __shfl_xor_sync(0xFFFFFFFFu, ct, off);
    }
    float si = CAT_RATE / fmaxf(sqrtf(ci), 1e-12f);
    float st = CAT_RATE / fmaxf(sqrtf(ct), 1e-12f);

    // cross-plane combine for fused-e output (lanes 0-7 consume)
    float o[8];
    #pragma unroll
    for (int j = 0; j < 8; j++) {
        float miv = __shfl_sync(0xFFFFFFFFu, m[j], (lane & 7) + 8);
        float mtv = __shfl_sync(0xFFFFFFFFu, m[j], (lane & 7) + 16);
        o[j] = (plane == 0) ? (m[j] + si * miv + st * mtv) : m[j];
    }

    if (lane < 24) {
        int grpid = (plane == 0) ? g : (plane == 1) ? (3 + g) : (6 + g);
        size_t grp = (size_t)BATCH * EMBED;
        float* dst = out + (size_t)grpid * grp + (size_t)i * EMBED + sub * 8;
        *(float4*)dst       = make_float4(o[0], o[1], o[2], o[3]);
        *(float4*)(dst + 4) = make_float4(o[4], o[5], o[6], o[7]);
    }
}

// ---------------- launch ------------------------------------------------------
extern "C" void kernel_launch(void* const* d_in, const int* in_sizes, int n_in,
                              void* d_out, int out_size) {
    const int*   uidx   = (const int*)  d_in[0];
    const int*   pidx   = (const int*)  d_in[1];
    const int*   nidx   = (const int*)  d_in[2];
    const int*   arows  = (const int*)  d_in[3];
    const int*   acols  = (const int*)  d_in[4];
    const float* avals  = (const float*)d_in[5];
    const float* E0     = (const float*)d_in[6];
    const float* Wimg   = (const float*)d_in[7];
    const float* Bimg   = (const float*)d_in[8];
    const float* Wtxt   = (const float*)d_in[9];
    const float* Btxt   = (const float*)d_in[10];
    float* out = (float*)d_out;

    __half *F0, *F1, *F2;
    cudaGetSymbolAddress((void**)&F0, g_F0);
    cudaGetSymbolAddress((void**)&F1, g_F1);
    cudaGetSymbolAddress((void**)&F2, g_F2);

    // histogram + packed ranks (8 edges/thread)
    k_hist<<<NB_HIST, 256>>>(arows);

    // CSR offsets (two-pass)
    k_scan_p1<<<SCAN_NB, SCAN_T>>>();
    k_scan_p3<<<SCAN_NB, SCAN_T>>>();

    // striped scatter (4 edges/thread, 1:9) + feature init
    k_scatter_init<<<SI_GRID, 256>>>(arows, acols, avals, E0, Wimg, Wtxt);

    // layer 1 (dense, LDG.128 gathers) + needflag marker; layer 2 filtered
    k_spmm_mark<<<SPMM_BLOCKS + MARK_BLOCKS, 256>>>(F0, F1, Bimg, Btxt, uidx, pidx, nidx);
    k_spmm_filt<<<SPMM_BLOCKS, 256>>>(F1, F2, Bimg, Btxt);

    // final: on-the-fly layer 3 + sum/mean/normalize/gather (+ scratch resets)
    k_final<<<FIN_BLOCKS + ZERO_BLOCKS, 256>>>(uidx, pidx, nidx, Bimg, Btxt, out);
}

// round 16
// speedup vs baseline: 1.0876x; 1.0876x over previous
#include <cuda_runtime.h>
#include <cuda_fp16.h>

#define N_USERS 50000
#define NN      100000        // total nodes
#define EMBED   64
#define FDIM    192           // 3 streams interleaved: [e | img | txt]
#define NEDGES  1600000
#define BATCH   4096
#define CAT_RATE 0.02f

// ---------------- device scratch ----------------------------------------------
__device__ __half g_F0[NN * FDIM];
__device__ __half g_F1[NN * FDIM];
__device__ __half g_F2[NN * FDIM];
__device__ int           g_count[NN];       // zero at load; re-zeroed each launch
__device__ int           g_rowstart[NN + 1];
__device__ unsigned char g_rank8[NEDGES];   // within-row rank (max deg << 256)
__device__ int           g_needflag[NN];    // rows needing F2; re-zeroed each launch
__device__ int2          g_edge[NEDGES];    // (col, val-as-int-bits), row-grouped
__device__ int           g_blocksums[256];

// ---------------- packed f32x2 helpers (sm_100 FFMA2, PTX-only) -----------------
__device__ __forceinline__ unsigned long long pack2(float x, float y) {
    unsigned long long r;
    asm("mov.b64 %0, {%1, %2};" : "=l"(r) : "f"(x), "f"(y));
    return r;
}
__device__ __forceinline__ float2 unpack2(unsigned long long p) {
    float2 f;
    asm("mov.b64 {%0, %1}, %2;" : "=f"(f.x), "=f"(f.y) : "l"(p));
    return f;
}
// acc = h(converted to f32x2) * vv + acc   (two IEEE rn-fused FMAs; bit-identical)
__device__ __forceinline__ void fma2h(unsigned long long& acc, __half2 h, unsigned long long vv) {
    float2 f = __half22float2(h);
    unsigned long long ff = pack2(f.x, f.y);
    asm("fma.rn.f32x2 %0, %1, %2, %0;" : "+l"(acc) : "l"(ff), "l"(vv));
}

// ---------------- pure hist (+packed rank), 8 edges/thread ---------------------
#define NB_HIST ((NEDGES / 8 + 255) / 256)      // 782

__global__ void k_hist(const int* __restrict__ rows) {
    int e8 = (blockIdx.x * blockDim.x + threadIdx.x) * 8;
    if (e8 < NEDGES) {
        int4 ra = *(const int4*)(rows + e8);
        int4 rb = *(const int4*)(rows + e8 + 4);
        unsigned int k0 = atomicAdd(&g_count[ra.x], 1);
        unsigned int k1 = atomicAdd(&g_count[ra.y], 1);
        unsigned int k2 = atomicAdd(&g_count[ra.z], 1);
        unsigned int k3 = atomicAdd(&g_count[ra.w], 1);
        unsigned int k4 = atomicAdd(&g_count[rb.x], 1);
        unsigned int k5 = atomicAdd(&g_count[rb.y], 1);
        unsigned int k6 = atomicAdd(&g_count[rb.z], 1);
        unsigned int k7 = atomicAdd(&g_count[rb.w], 1);
        uint2 packed;
        packed.x = (k0 & 0xFF) | ((k1 & 0xFF) << 8) | ((k2 & 0xFF) << 16) | ((k3 & 0xFF) << 24);
        packed.y = (k4 & 0xFF) | ((k5 & 0xFF) << 8) | ((k6 & 0xFF) << 16) | ((k7 & 0xFF) << 24);
        *(uint2*)(g_rank8 + e8) = packed;
    }
}

// ---------------- scan (NN elements), two-pass ---------------------------------
#define SCAN_T 512
#define SCAN_NB ((NN + SCAN_T - 1) / SCAN_T)   // 196

__global__ void k_scan_p1() {
    __shared__ int sm[SCAN_T];
    int i = blockIdx.x * SCAN_T + threadIdx.x;
    sm[threadIdx.x] = (i < NN) ? g_count[i] : 0;
    __syncthreads();
    for (int off = SCAN_T / 2; off > 0; off >>= 1) {
        if (threadIdx.x < off) sm[threadIdx.x] += sm[threadIdx.x + off];
        __syncthreads();
    }
    if (threadIdx.x == 0) g_blocksums[blockIdx.x] = sm[0];
}

__global__ void k_scan_p3() {
    __shared__ int sm[SCAN_T];
    __shared__ int s_off;
    int contrib = (threadIdx.x < blockIdx.x) ? g_blocksums[threadIdx.x] : 0;
    sm[threadIdx.x] = contrib;
    __syncthreads();
    for (int off = SCAN_T / 2; off > 0; off >>= 1) {
        if (threadIdx.x < off) sm[threadIdx.x] += sm[threadIdx.x + off];
        __syncthreads();
    }
    if (threadIdx.x == 0) s_off = sm[0];
    __syncthreads();
    int i = blockIdx.x * SCAN_T + threadIdx.x;
    int v = (i < NN) ? g_count[i] : 0;
    sm[threadIdx.x] = v;
    __syncthreads();
    for (int off = 1; off < SCAN_T; off <<= 1) {
        int add = (threadIdx.x >= off) ? sm[threadIdx.x - off] : 0;
        __syncthreads();
        sm[threadIdx.x] += add;
        __syncthreads();
    }
    int excl = sm[threadIdx.x] - v + s_off;
    if (i < NN) g_rowstart[i] = excl;
    if (i == 0) g_rowstart[NN] = NEDGES;
}

// ---------------- fused: scatter (4 edges/thread) + feature init, 1:9 stripe ---
#define NB_SCAT  ((NEDGES / 4 + 255) / 256)      // 1563
#define NB_INITE ((NN * EMBED / 4 + 255) / 256)  // 6250
#define NB_TILES (NN / 32)                       // 3125
#define NB_INIT  (NB_INITE + 2 * NB_TILES)       // 12500
#define SI_GRID  (NB_SCAT * 9)                   // 14067: g%9==0 -> scatter

__global__ void k_scatter_init(const int* __restrict__ rows, const int* __restrict__ cols,
                               const float* __restrict__ vals,
                               const float* __restrict__ E0,
                               const float* __restrict__ Wimg,
                               const float* __restrict__ Wtxt) {
    __shared__ float sm[64][33];
    int g = blockIdx.x;
    if (g % 9 == 0) {
        int sb = g / 9;
        int e4 = (sb * 256 + threadIdx.x) * 4;
        if (e4 < NEDGES) {
            int4   r4 = *(const int4*)(rows + e4);
            int4   c4 = *(const int4*)(cols + e4);
            float4 v4 = *(const float4*)(vals + e4);
            unsigned int kk = *(const unsigned int*)(g_rank8 + e4);
            g_edge[g_rowstart[r4.x] + ( kk        & 0xFF)] = make_int2(c4.x, __float_as_int(v4.x));
            g_edge[g_rowstart[r4.y] + ((kk >>  8) & 0xFF)] = make_int2(c4.y, __float_as_int(v4.y));
            g_edge[g_rowstart[r4.z] + ((kk >> 16) & 0xFF)] = make_int2(c4.z, __float_as_int(v4.z));
            g_edge[g_rowstart[r4.w] + ((kk >> 24) & 0xFF)] = make_int2(c4.w, __float_as_int(v4.w));
        }
        return;
    }
    int b = g - (g / 9) - 1;
    if (b >= NB_INIT) return;
    if (b < NB_INITE) {
        int i = b * 256 + threadIdx.x;
        if (i < NN * (EMBED / 4)) {
            int n  = i >> 4;
            int d4 = (i & 15) * 4;
            float4 v = ((const float4*)E0)[i];
            __half2* dst = (__half2*)(g_F0 + (size_t)n * FDIM + d4);
            dst[0] = __floats2half2_rn(v.x, v.y);
            dst[1] = __floats2half2_rn(v.z, v.w);
        }
        return;
    }
    b -= NB_INITE;
    const float* W = (b < NB_TILES) ? Wimg : Wtxt;
    int plane_off  = (b < NB_TILES) ? 64 : 128;
    int tile = (b < NB_TILES) ? b : (b - NB_TILES);
    int n0 = tile * 32;
    int tx = threadIdx.x & 31;
    int ty = threadIdx.x >> 5;
    #pragma unroll
    for (int k = 0; k < 8; k++) {
        int d = k * 8 + ty;
        sm[d][tx] = W[(size_t)d * NN + n0 + tx];
    }
    __syncthreads();
    #pragma unroll
    for (int k = 0; k < 4; k++) {
        int row = k * 8 + ty;
        int n = n0 + row;
        #pragma unroll
        for (int dk = 0; dk < 2; dk++) {
            int d = dk * 32 + tx;
            g_F0[(size_t)n * FDIM + plane_off + d] = __float2half_rn(sm[d][row]);
        }
    }
}

// ---------------- SPMM row body (fp16 in/out, packed f32x2 accum) ---------------
__device__ __forceinline__ void spmm_row(int row, int lane,
                                         const __half* __restrict__ A, __half* __restrict__ B,
                                         const float* __restrict__ bias_i,
                                         const float* __restrict__ bias_t) {
    int s = g_rowstart[row];
    int e = g_rowstart[row + 1];
    unsigned long long accA = 0ull, accI = 0ull, accT = 0ull;   // packed (0.f, 0.f)
    int k = s;
    for (; k + 1 < e; k += 2) {
        int2  eA = __ldg(&g_edge[k]);
        int2  eB = __ldg(&g_edge[k + 1]);
        float vA = __int_as_float(eA.y);
        float vB = __int_as_float(eB.y);
        const __half2* xA = (const __half2*)(A + (size_t)eA.x * FDIM);
        const __half2* xB = (const __half2*)(A + (size_t)eB.x * FDIM);
        __half2 hA0 = xA[lane], hA1 = xA[32 + lane], hA2 = xA[64 + lane];
        __half2 hB0 = xB[lane], hB1 = xB[32 + lane], hB2 = xB[64 + lane];
        unsigned long long vvA = pack2(vA, vA);
        unsigned long long vvB = pack2(vB, vB);
        fma2h(accA, hA0, vvA); fma2h(accI, hA1, vvA); fma2h(accT, hA2, vvA);
        fma2h(accA, hB0, vvB); fma2h(accI, hB1, vvB); fma2h(accT, hB2, vvB);
    }
    if (k < e) {
        int2  ed = __ldg(&g_edge[k]);
        float v  = __int_as_float(ed.y);
        const __half2* xr = (const __half2*)(A + (size_t)ed.x * FDIM);
        unsigned long long vv = pack2(v, v);
        fma2h(accA, xr[lane], vv);
        fma2h(accI, xr[32 + lane], vv);
        fma2h(accT, xr[64 + lane], vv);
    }
    float2 a = unpack2(accA);
    float2 i = unpack2(accI);
    float2 t = unpack2(accT);
    int doff = lane * 2;
    float2 bi = *(const float2*)(bias_i + doff);
    float2 bt = *(const float2*)(bias_t + doff);
    __half2* br = (__half2*)(B + (size_t)row * FDIM);
    br[lane]      = __floats2half2_rn(a.x, a.y);
    br[32 + lane] = __floats2half2_rn(i.x + bi.x, i.y + bi.y);
    br[64 + lane] = __floats2half2_rn(t.x + bt.x, t.y + bt.y);
}

// ---------------- SPMM1 (dense) + need-marker trailing blocks -------------------
#define SPMM_BLOCKS ((NN * 32 + 255) / 256)     // 12500
#define MARK_BLOCKS ((3 * BATCH) / 8)           // 1536 (one warp per target row)

__global__ void k_spmm_mark(const __half* __restrict__ A, __half* __restrict__ B,
                            const float* __restrict__ bias_i, const float* __restrict__ bias_t,
                            const int* __restrict__ uidx, const int* __restrict__ pidx,
                            const int* __restrict__ nidx) {
    int lane = threadIdx.x & 31;
    if (blockIdx.x >= SPMM_BLOCKS) {
        int warp = ((blockIdx.x - SPMM_BLOCKS) * blockDim.x + threadIdx.x) >> 5;
        int g = warp / BATCH;
        int i = warp - g * BATCH;
        int idx = (g == 0) ? __ldg(&uidx[i]) : (g == 1) ? __ldg(&pidx[i]) : __ldg(&nidx[i]);
        int row = (g == 0) ? idx : (N_USERS + idx);
        if (lane == 0) g_needflag[row] = 1;
        int s = g_rowstart[row];
        int e = g_rowstart[row + 1];
        for (int k = s + lane; k < e; k += 32)
            g_needflag[g_edge[k].x] = 1;
        return;
    }
    int warp = (blockIdx.x * blockDim.x + threadIdx.x) >> 5;
    if (warp >= NN) return;
    spmm_row(warp, lane, A, B, bias_i, bias_t);
}

// ---------------- SPMM2 (filtered by needflag) ---------------------------------
__global__ void k_spmm_filt(const __half* __restrict__ A, __half* __restrict__ B,
                            const float* __restrict__ bias_i, const float* __restrict__ bias_t) {
    int warp = (blockIdx.x * blockDim.x + threadIdx.x) >> 5;
    int lane = threadIdx.x & 31;
    if (warp >= NN) return;
    if (g_needflag[warp] == 0) return;
    spmm_row(warp, lane, A, B, bias_i, bias_t);
}

// ---------------- final: on-the-fly layer-3 + sum + mean + l2 + gathers -------
#define FIN_BLOCKS ((3 * BATCH * 32 + 255) / 256)          // 1536
#define ZERO_N     (2 * NN)                                // count + needflag
#define ZERO_BLOCKS ((ZERO_N + 255) / 256)                 // 782

__global__ void k_final(const int* __restrict__ uidx, const int* __restrict__ pidx,
                        const int* __restrict__ nidx,
                        const float* __restrict__ bias_i, const float* __restrict__ bias_t,
                        float* __restrict__ out) {
    if (blockIdx.x >= FIN_BLOCKS) {
        int i = (blockIdx.x - FIN_BLOCKS) * 256 + threadIdx.x;
        if (i < NN) g_count[i] = 0;
        else if (i < 2 * NN) g_needflag[i - NN] = 0;
        return;
    }
    int warp = (blockIdx.x * blockDim.x + threadIdx.x) >> 5;
    int lane = threadIdx.x & 31;
    int g = warp / BATCH;
    int i = warp - g * BATCH;
    int idx = (g == 0) ? __ldg(&uidx[i]) : (g == 1) ? __ldg(&pidx[i]) : __ldg(&nidx[i]);
    int row = (g == 0) ? idx : (N_USERS + idx);

    // hoist stored-layer row loads: independent of the edge-gather chain
    size_t base = (size_t)row * FDIM;
    const __half2* r0 = (const __half2*)(g_F0 + base);
    const __half2* r1 = (const __half2*)(g_F1 + base);
    const __half2* r2 = (const __half2*)(g_F2 + base);
    __half2 h00 = r0[lane],      h01 = r0[32 + lane], h02 = r0[64 + lane];
    __half2 h10 = r1[lane],      h11 = r1[32 + lane], h12 = r1[64 + lane];
    __half2 h20 = r2[lane],      h21 = r2[32 + lane], h22 = r2[64 + lane];

    // ---- layer-3 propagation on the fly from F2 (packed f32x2 accum) ----
    int s = g_rowstart[row];
    int e = g_rowstart[row + 1];
    unsigned long long accA = 0ull, accI = 0ull, accT = 0ull;
    int k = s;
    for (; k + 1 < e; k += 2) {
        int2  eA = __ldg(&g_edge[k]);
        int2  eB = __ldg(&g_edge[k + 1]);
        float vA = __int_as_float(eA.y);
        float vB = __int_as_float(eB.y);
        const __half2* xA = (const __half2*)(g_F2 + (size_t)eA.x * FDIM);
        const __half2* xB = (const __half2*)(g_F2 + (size_t)eB.x * FDIM);
        __half2 hA0 = xA[lane], hA1 = xA[32 + lane], hA2 = xA[64 + lane];
        __half2 hB0 = xB[lane], hB1 = xB[32 + lane], hB2 = xB[64 + lane];
        unsigned long long vvA = pack2(vA, vA);
        unsigned long long vvB = pack2(vB, vB);
        fma2h(accA, hA0, vvA); fma2h(accI, hA1, vvA); fma2h(accT, hA2, vvA);
        fma2h(accA, hB0, vvB); fma2h(accI, hB1, vvB); fma2h(accT, hB2, vvB);
    }
    if (k < e) {
        int2  ed = __ldg(&g_edge[k]);
        float v  = __int_as_float(ed.y);
        const __half2* xr = (const __half2*)(g_F2 + (size_t)ed.x * FDIM);
        unsigned long long vv = pack2(v, v);
        fma2h(accA, xr[lane], vv);
        fma2h(accI, xr[32 + lane], vv);
        fma2h(accT, xr[64 + lane], vv);
    }
    float2 a3 = unpack2(accA);
    float2 i3 = unpack2(accI);
    float2 t3 = unpack2(accT);
    int doff = lane * 2;
    float2 bi = *(const float2*)(bias_i + doff);
    float2 bt = *(const float2*)(bias_t + doff);
    i3.x += bi.x; i3.y += bi.y;
    t3.x += bt.x; t3.y += bt.y;

    const float inv = 0.25f;
    float2 me, mi, mt;
    {
        float2 a = __half22float2(h00), b = __half22float2(h10), c = __half22float2(h20);
        me.x = (a.x + b.x + c.x + a3.x) * inv;  me.y = (a.y + b.y + c.y + a3.y) * inv;
    }
    {
        float2 a = __half22float2(h01), b = __half22float2(h11), c = __half22float2(h21);
        mi.x = (a.x + b.x + c.x + i3.x) * inv;  mi.y = (a.y + b.y + c.y + i3.y) * inv;
    }
    {
        float2 a = __half22float2(h02), b = __half22float2(h12), c = __half22float2(h22);
        mt.x = (a.x + b.x + c.x + t3.x) * inv;  mt.y = (a.y + b.y + c.y + t3.y) * inv;
    }

    float sqi = mi.x * mi.x + mi.y * mi.y;
    float sqt = mt.x * mt.x + mt.y * mt.y;
    #pragma unroll
    for (int off = 16; off > 0; off >>= 1) {
        sqi += __shfl_xor_sync(0xFFFFFFFFu, sqi, off);
        sqt += __shfl_xor_sync(0xFFFFFFFFu, sqt, off);
    }
    float si = CAT_RATE / fmaxf(sqrtf(sqi), 1e-12f);
    float st = CAT_RATE / fmaxf(sqrtf(sqt), 1e-12f);

    float2 oe;
    oe.x = me.x + si * mi.x + st * mt.x;
    oe.y = me.y + si * mi.y + st * mt.y;

    size_t slot = (size_t)i * EMBED + doff;
    size_t grp  = (size_t)BATCH * EMBED;
    *(float2*)(out + (size_t)g * grp + slot)       = oe;
    *(float2*)(out + (size_t)(3 + g) * grp + slot) = mi;
    *(float2*)(out + (size_t)(6 + g) * grp + slot) = mt;
}

// ---------------- launch ------------------------------------------------------
extern "C" void kernel_launch(void* const* d_in, const int* in_sizes, int n_in,
                              void* d_out, int out_size) {
    const int*   uidx   = (const int*)  d_in[0];
    const int*   pidx   = (const int*)  d_in[1];
    const int*   nidx   = (const int*)  d_in[2];
    const int*   arows  = (const int*)  d_in[3];
    const int*   acols  = (const int*)  d_in[4];
    const float* avals  = (const float*)d_in[5];
    const float* E0     = (const float*)d_in[6];
    const float* Wimg   = (const float*)d_in[7];
    const float* Bimg   = (const float*)d_in[8];
    const float* Wtxt   = (const float*)d_in[9];
    const float* Btxt   = (const float*)d_in[10];
    float* out = (float*)d_out;

    __half *F0, *F1, *F2;
    cudaGetSymbolAddress((void**)&F0, g_F0);
    cudaGetSymbolAddress((void**)&F1, g_F1);
    cudaGetSymbolAddress((void**)&F2, g_F2);

    // histogram + packed ranks (8 edges/thread)
    k_hist<<<NB_HIST, 256>>>(arows);

    // CSR offsets (two-pass)
    k_scan_p1<<<SCAN_NB, SCAN_T>>>();
    k_scan_p3<<<SCAN_NB, SCAN_T>>>();

    // striped scatter (4 edges/thread, 1:9) + feature init
    k_scatter_init<<<SI_GRID, 256>>>(arows, acols, avals, E0, Wimg, Wtxt);

    // layer 1 (dense, FFMA2) + needflag marker; layer 2 filtered
    k_spmm_mark<<<SPMM_BLOCKS + MARK_BLOCKS, 256>>>(F0, F1, Bimg, Btxt, uidx, pidx, nidx);
    k_spmm_filt<<<SPMM_BLOCKS, 256>>>(F1, F2, Bimg, Btxt);

    // final: on-the-fly layer 3 + sum/mean/normalize/gather (+ scratch resets)
    k_final<<<FIN_BLOCKS + ZERO_BLOCKS, 256>>>(uidx, pidx, nidx, Bimg, Btxt, out);
}

// round 17
// speedup vs baseline: 1.2737x; 1.1711x over previous
#include <cuda_runtime.h>
#include <cuda_fp16.h>

#define N_USERS 50000
#define NN      100000        // total nodes
#define EMBED   64
#define FDIM    192           // 3 streams interleaved: [e | img | txt]
#define NEDGES  1600000
#define BATCH   4096
#define CAT_RATE 0.02f

// ---------------- device scratch ----------------------------------------------
__device__ __half g_F0[NN * FDIM];
__device__ __half g_F1[NN * FDIM];
__device__ __half g_F2[NN * FDIM];
__device__ int           g_count[NN];       // zero at load; re-zeroed each launch
__device__ int           g_rowstart[NN + 1];
__device__ unsigned char g_rank8[NEDGES];   // within-row rank (max deg << 256)
__device__ int           g_needflag[NN];    // rows needing F2; re-zeroed each launch
__device__ int2          g_edge[NEDGES];    // (col, val-as-int-bits), row-grouped
__device__ int           g_blocksums[256];

// ---------------- pure hist (+packed rank), 16 edges/thread --------------------
#define NB_HIST ((NEDGES / 16 + 255) / 256)     // 391

__global__ void k_hist(const int* __restrict__ rows) {
    int e16 = (blockIdx.x * blockDim.x + threadIdx.x) * 16;
    if (e16 < NEDGES) {
        int4 ra = *(const int4*)(rows + e16);
        int4 rb = *(const int4*)(rows + e16 + 4);
        int4 rc = *(const int4*)(rows + e16 + 8);
        int4 rd = *(const int4*)(rows + e16 + 12);
        unsigned int k0  = atomicAdd(&g_count[ra.x], 1);
        unsigned int k1  = atomicAdd(&g_count[ra.y], 1);
        unsigned int k2  = atomicAdd(&g_count[ra.z], 1);
        unsigned int k3  = atomicAdd(&g_count[ra.w], 1);
        unsigned int k4  = atomicAdd(&g_count[rb.x], 1);
        unsigned int k5  = atomicAdd(&g_count[rb.y], 1);
        unsigned int k6  = atomicAdd(&g_count[rb.z], 1);
        unsigned int k7  = atomicAdd(&g_count[rb.w], 1);
        unsigned int k8  = atomicAdd(&g_count[rc.x], 1);
        unsigned int k9  = atomicAdd(&g_count[rc.y], 1);
        unsigned int k10 = atomicAdd(&g_count[rc.z], 1);
        unsigned int k11 = atomicAdd(&g_count[rc.w], 1);
        unsigned int k12 = atomicAdd(&g_count[rd.x], 1);
        unsigned int k13 = atomicAdd(&g_count[rd.y], 1);
        unsigned int k14 = atomicAdd(&g_count[rd.z], 1);
        unsigned int k15 = atomicAdd(&g_count[rd.w], 1);
        uint4 packed;
        packed.x = (k0  & 0xFF) | ((k1  & 0xFF) << 8) | ((k2  & 0xFF) << 16) | ((k3  & 0xFF) << 24);
        packed.y = (k4  & 0xFF) | ((k5  & 0xFF) << 8) | ((k6  & 0xFF) << 16) | ((k7  & 0xFF) << 24);
        packed.z = (k8  & 0xFF) | ((k9  & 0xFF) << 8) | ((k10 & 0xFF) << 16) | ((k11 & 0xFF) << 24);
        packed.w = (k12 & 0xFF) | ((k13 & 0xFF) << 8) | ((k14 & 0xFF) << 16) | ((k15 & 0xFF) << 24);
        *(uint4*)(g_rank8 + e16) = packed;
    }
}

// ---------------- scan (NN elements), two-pass ---------------------------------
#define SCAN_T 512
#define SCAN_NB ((NN + SCAN_T - 1) / SCAN_T)   // 196

__global__ void k_scan_p1() {
    __shared__ int sm[SCAN_T];
    int i = blockIdx.x * SCAN_T + threadIdx.x;
    sm[threadIdx.x] = (i < NN) ? g_count[i] : 0;
    __syncthreads();
    for (int off = SCAN_T / 2; off > 0; off >>= 1) {
        if (threadIdx.x < off) sm[threadIdx.x] += sm[threadIdx.x + off];
        __syncthreads();
    }
    if (threadIdx.x == 0) g_blocksums[blockIdx.x] = sm[0];
}

__global__ void k_scan_p3() {
    __shared__ int sm[SCAN_T];
    __shared__ int s_off;
    int contrib = (threadIdx.x < blockIdx.x) ? g_blocksums[threadIdx.x] : 0;
    sm[threadIdx.x] = contrib;
    __syncthreads();
    for (int off = SCAN_T / 2; off > 0; off >>= 1) {
        if (threadIdx.x < off) sm[threadIdx.x] += sm[threadIdx.x + off];
        __syncthreads();
    }
    if (threadIdx.x == 0) s_off = sm[0];
    __syncthreads();
    int i = blockIdx.x * SCAN_T + threadIdx.x;
    int v = (i < NN) ? g_count[i] : 0;
    sm[threadIdx.x] = v;
    __syncthreads();
    for (int off = 1; off < SCAN_T; off <<= 1) {
        int add = (threadIdx.x >= off) ? sm[threadIdx.x - off] : 0;
        __syncthreads();
        sm[threadIdx.x] += add;
        __syncthreads();
    }
    int excl = sm[threadIdx.x] - v + s_off;
    if (i < NN) g_rowstart[i] = excl;
    if (i == 0) g_rowstart[NN] = NEDGES;
}

// ---------------- fused: scatter (4 edges/thread) + feature init, 1:9 stripe ---
#define NB_SCAT  ((NEDGES / 4 + 255) / 256)      // 1563
#define NB_INITE ((NN * EMBED / 4 + 255) / 256)  // 6250
#define NB_TILES (NN / 32)                       // 3125
#define NB_INIT  (NB_INITE + 2 * NB_TILES)       // 12500
#define SI_GRID  (NB_SCAT * 9)                   // 14067: g%9==0 -> scatter

__global__ void k_scatter_init(const int* __restrict__ rows, const int* __restrict__ cols,
                               const float* __restrict__ vals,
                               const float* __restrict__ E0,
                               const float* __restrict__ Wimg,
                               const float* __restrict__ Wtxt) {
    __shared__ float sm[64][33];
    int g = blockIdx.x;
    if (g % 9 == 0) {
        int sb = g / 9;
        int e4 = (sb * 256 + threadIdx.x) * 4;
        if (e4 < NEDGES) {
            int4   r4 = *(const int4*)(rows + e4);
            int4   c4 = *(const int4*)(cols + e4);
            float4 v4 = *(const float4*)(vals + e4);
            unsigned int kk = *(const unsigned int*)(g_rank8 + e4);
            g_edge[g_rowstart[r4.x] + ( kk        & 0xFF)] = make_int2(c4.x, __float_as_int(v4.x));
            g_edge[g_rowstart[r4.y] + ((kk >>  8) & 0xFF)] = make_int2(c4.y, __float_as_int(v4.y));
            g_edge[g_rowstart[r4.z] + ((kk >> 16) & 0xFF)] = make_int2(c4.z, __float_as_int(v4.z));
            g_edge[g_rowstart[r4.w] + ((kk >> 24) & 0xFF)] = make_int2(c4.w, __float_as_int(v4.w));
        }
        return;
    }
    int b = g - (g / 9) - 1;
    if (b >= NB_INIT) return;
    if (b < NB_INITE) {
        int i = b * 256 + threadIdx.x;
        if (i < NN * (EMBED / 4)) {
            int n  = i >> 4;
            int d4 = (i & 15) * 4;
            float4 v = ((const float4*)E0)[i];
            __half2* dst = (__half2*)(g_F0 + (size_t)n * FDIM + d4);
            dst[0] = __floats2half2_rn(v.x, v.y);
            dst[1] = __floats2half2_rn(v.z, v.w);
        }
        return;
    }
    b -= NB_INITE;
    const float* W = (b < NB_TILES) ? Wimg : Wtxt;
    int plane_off  = (b < NB_TILES) ? 64 : 128;
    int tile = (b < NB_TILES) ? b : (b - NB_TILES);
    int n0 = tile * 32;
    int tx = threadIdx.x & 31;
    int ty = threadIdx.x >> 5;
    #pragma unroll
    for (int k = 0; k < 8; k++) {
        int d = k * 8 + ty;
        sm[d][tx] = W[(size_t)d * NN + n0 + tx];
    }
    __syncthreads();
    #pragma unroll
    for (int k = 0; k < 4; k++) {
        int row = k * 8 + ty;
        int n = n0 + row;
        #pragma unroll
        for (int dk = 0; dk < 2; dk++) {
            int d = dk * 32 + tx;
            g_F0[(size_t)n * FDIM + plane_off + d] = __float2half_rn(sm[d][row]);
        }
    }
}

// ---------------- SPMM row body: 4 edges in flight (fp32 accum) ----------------
__device__ __forceinline__ void spmm_row(int row, int lane,
                                         const __half* __restrict__ A, __half* __restrict__ B,
                                         const float* __restrict__ bias_i,
                                         const float* __restrict__ bias_t) {
    int s = g_rowstart[row];
    int e = g_rowstart[row + 1];
    float a0 = 0.f, a1 = 0.f, i0 = 0.f, i1 = 0.f, t0 = 0.f, t1 = 0.f;
    int k = s;
    for (; k + 3 < e; k += 4) {
        int2 eA = __ldg(&g_edge[k]);
        int2 eB = __ldg(&g_edge[k + 1]);
        int2 eC = __ldg(&g_edge[k + 2]);
        int2 eD = __ldg(&g_edge[k + 3]);
        const __half2* xA = (const __half2*)(A + (size_t)eA.x * FDIM);
        const __half2* xB = (const __half2*)(A + (size_t)eB.x * FDIM);
        const __half2* xC = (const __half2*)(A + (size_t)eC.x * FDIM);
        const __half2* xD = (const __half2*)(A + (size_t)eD.x * FDIM);
        float vA = __int_as_float(eA.y), vB = __int_as_float(eB.y);
        float vC = __int_as_float(eC.y), vD = __int_as_float(eD.y);
        __half2 hA0 = xA[lane], hA1 = xA[32 + lane], hA2 = xA[64 + lane];
        __half2 hB0 = xB[lane], hB1 = xB[32 + lane], hB2 = xB[64 + lane];
        __half2 hC0 = xC[lane], hC1 = xC[32 + lane], hC2 = xC[64 + lane];
        __half2 hD0 = xD[lane], hD1 = xD[32 + lane], hD2 = xD[64 + lane];
        float2 f;
        f = __half22float2(hA0); a0 += vA * f.x; a1 += vA * f.y;
        f = __half22float2(hA1); i0 += vA * f.x; i1 += vA * f.y;
        f = __half22float2(hA2); t0 += vA * f.x; t1 += vA * f.y;
        f = __half22float2(hB0); a0 += vB * f.x; a1 += vB * f.y;
        f = __half22float2(hB1); i0 += vB * f.x; i1 += vB * f.y;
        f = __half22float2(hB2); t0 += vB * f.x; t1 += vB * f.y;
        f = __half22float2(hC0); a0 += vC * f.x; a1 += vC * f.y;
        f = __half22float2(hC1); i0 += vC * f.x; i1 += vC * f.y;
        f = __half22float2(hC2); t0 += vC * f.x; t1 += vC * f.y;
        f = __half22float2(hD0); a0 += vD * f.x; a1 += vD * f.y;
        f = __half22float2(hD1); i0 += vD * f.x; i1 += vD * f.y;
        f = __half22float2(hD2); t0 += vD * f.x; t1 += vD * f.y;
    }
    for (; k < e; k++) {
        int2  ed = __ldg(&g_edge[k]);
        float v  = __int_as_float(ed.y);
        const __half2* xr = (const __half2*)(A + (size_t)ed.x * FDIM);
        float2 f0 = __half22float2(xr[lane]);
        float2 f1 = __half22float2(xr[32 + lane]);
        float2 f2 = __half22float2(xr[64 + lane]);
        a0 += v * f0.x; a1 += v * f0.y;
        i0 += v * f1.x; i1 += v * f1.y;
        t0 += v * f2.x; t1 += v * f2.y;
    }
    int doff = lane * 2;
    float2 bi = *(const float2*)(bias_i + doff);
    float2 bt = *(const float2*)(bias_t + doff);
    __half2* br = (__half2*)(B + (size_t)row * FDIM);
    br[lane]      = __floats2half2_rn(a0, a1);
    br[32 + lane] = __floats2half2_rn(i0 + bi.x, i1 + bi.y);
    br[64 + lane] = __floats2half2_rn(t0 + bt.x, t1 + bt.y);
}

// ---------------- SPMM1 (dense) + need-marker trailing blocks -------------------
#define SPMM_BLOCKS ((NN * 32 + 255) / 256)     // 12500
#define MARK_BLOCKS ((3 * BATCH) / 8)           // 1536 (one warp per target row)

__global__ void k_spmm_mark(const __half* __restrict__ A, __half* __restrict__ B,
                            const float* __restrict__ bias_i, const float* __restrict__ bias_t,
                            const int* __restrict__ uidx, const int* __restrict__ pidx,
                            const int* __restrict__ nidx) {
    int lane = threadIdx.x & 31;
    if (blockIdx.x >= SPMM_BLOCKS) {
        int warp = ((blockIdx.x - SPMM_BLOCKS) * blockDim.x + threadIdx.x) >> 5;
        int g = warp / BATCH;
        int i = warp - g * BATCH;
        int idx = (g == 0) ? __ldg(&uidx[i]) : (g == 1) ? __ldg(&pidx[i]) : __ldg(&nidx[i]);
        int row = (g == 0) ? idx : (N_USERS + idx);
        if (lane == 0) g_needflag[row] = 1;
        int s = g_rowstart[row];
        int e = g_rowstart[row + 1];
        for (int k = s + lane; k < e; k += 32)
            g_needflag[g_edge[k].x] = 1;
        return;
    }
    int warp = (blockIdx.x * blockDim.x + threadIdx.x) >> 5;
    if (warp >= NN) return;
    spmm_row(warp, lane, A, B, bias_i, bias_t);
}

// ---------------- SPMM2 (filtered by needflag) ---------------------------------
__global__ void k_spmm_filt(const __half* __restrict__ A, __half* __restrict__ B,
                            const float* __restrict__ bias_i, const float* __restrict__ bias_t) {
    int warp = (blockIdx.x * blockDim.x + threadIdx.x) >> 5;
    int lane = threadIdx.x & 31;
    if (warp >= NN) return;
    if (g_needflag[warp] == 0) return;
    spmm_row(warp, lane, A, B, bias_i, bias_t);
}

// ---------------- final: on-the-fly layer-3 + sum + mean + l2 + gathers -------
#define FIN_BLOCKS ((3 * BATCH * 32 + 255) / 256)          // 1536
#define ZERO_N     (2 * NN)                                // count + needflag
#define ZERO_BLOCKS ((ZERO_N + 255) / 256)                 // 782

__global__ void k_final(const int* __restrict__ uidx, const int* __restrict__ pidx,
                        const int* __restrict__ nidx,
                        const float* __restrict__ bias_i, const float* __restrict__ bias_t,
                        float* __restrict__ out) {
    if (blockIdx.x >= FIN_BLOCKS) {
        int i = (blockIdx.x - FIN_BLOCKS) * 256 + threadIdx.x;
        if (i < NN) g_count[i] = 0;
        else if (i < 2 * NN) g_needflag[i - NN] = 0;
        return;
    }
    int warp = (blockIdx.x * blockDim.x + threadIdx.x) >> 5;
    int lane = threadIdx.x & 31;
    int g = warp / BATCH;
    int i = warp - g * BATCH;
    int idx = (g == 0) ? __ldg(&uidx[i]) : (g == 1) ? __ldg(&pidx[i]) : __ldg(&nidx[i]);
    int row = (g == 0) ? idx : (N_USERS + idx);

    // hoist stored-layer row loads: independent of the edge-gather chain
    size_t base = (size_t)row * FDIM;
    const __half2* r0 = (const __half2*)(g_F0 + base);
    const __half2* r1 = (const __half2*)(g_F1 + base);
    const __half2* r2 = (const __half2*)(g_F2 + base);
    __half2 h00 = r0[lane],      h01 = r0[32 + lane], h02 = r0[64 + lane];
    __half2 h10 = r1[lane],      h11 = r1[32 + lane], h12 = r1[64 + lane];
    __half2 h20 = r2[lane],      h21 = r2[32 + lane], h22 = r2[64 + lane];

    // ---- layer-3 propagation on the fly from F2 (fp32 accum), unrolled x2 ----
    int s = g_rowstart[row];
    int e = g_rowstart[row + 1];
    float a0 = 0.f, a1 = 0.f, i0 = 0.f, i1 = 0.f, t0 = 0.f, t1 = 0.f;
    int k = s;
    for (; k + 1 < e; k += 2) {
        int2  eA = __ldg(&g_edge[k]);
        int2  eB = __ldg(&g_edge[k + 1]);
        float vA = __int_as_float(eA.y);
        float vB = __int_as_float(eB.y);
        const __half2* xA = (const __half2*)(g_F2 + (size_t)eA.x * FDIM);
        const __half2* xB = (const __half2*)(g_F2 + (size_t)eB.x * FDIM);
        float2 fA0 = __half22float2(xA[lane]);
        float2 fA1 = __half22float2(xA[32 + lane]);
        float2 fA2 = __half22float2(xA[64 + lane]);
        float2 fB0 = __half22float2(xB[lane]);
        float2 fB1 = __half22float2(xB[32 + lane]);
        float2 fB2 = __half22float2(xB[64 + lane]);
        a0 += vA * fA0.x; a1 += vA * fA0.y;
        i0 += vA * fA1.x; i1 += vA * fA1.y;
        t0 += vA * fA2.x; t1 += vA * fA2.y;
        a0 += vB * fB0.x; a1 += vB * fB0.y;
        i0 += vB * fB1.x; i1 += vB * fB1.y;
        t0 += vB * fB2.x; t1 += vB * fB2.y;
    }
    if (k < e) {
        int2  ed = __ldg(&g_edge[k]);
        float v  = __int_as_float(ed.y);
        const __half2* xr = (const __half2*)(g_F2 + (size_t)ed.x * FDIM);
        float2 f0 = __half22float2(xr[lane]);
        float2 f1 = __half22float2(xr[32 + lane]);
        float2 f2 = __half22float2(xr[64 + lane]);
        a0 += v * f0.x; a1 += v * f0.y;
        i0 += v * f1.x; i1 += v * f1.y;
        t0 += v * f2.x; t1 += v * f2.y;
    }
    int doff = lane * 2;
    float2 bi = *(const float2*)(bias_i + doff);
    float2 bt = *(const float2*)(bias_t + doff);
    i0 += bi.x; i1 += bi.y;
    t0 += bt.x; t1 += bt.y;

    const float inv = 0.25f;
    float2 me, mi, mt;
    {
        float2 a = __half22float2(h00), b = __half22float2(h10), c = __half22float2(h20);
        me.x = (a.x + b.x + c.x + a0) * inv;  me.y = (a.y + b.y + c.y + a1) * inv;
    }
    {
        float2 a = __half22float2(h01), b = __half22float2(h11), c = __half22float2(h21);
        mi.x = (a.x + b.x + c.x + i0) * inv;  mi.y = (a.y + b.y + c.y + i1) * inv;
    }
    {
        float2 a = __half22float2(h02), b = __half22float2(h12), c = __half22float2(h22);
        mt.x = (a.x + b.x + c.x + t0) * inv;  mt.y = (a.y + b.y + c.y + t1) * inv;
    }

    float sqi = mi.x * mi.x + mi.y * mi.y;
    float sqt = mt.x * mt.x + mt.y * mt.y;
    #pragma unroll
    for (int off = 16; off > 0; off >>= 1) {
        sqi += __shfl_xor_sync(0xFFFFFFFFu, sqi, off);
        sqt += __shfl_xor_sync(0xFFFFFFFFu, sqt, off);
    }
    float si = CAT_RATE / fmaxf(sqrtf(sqi), 1e-12f);
    float st = CAT_RATE / fmaxf(sqrtf(sqt), 1e-12f);

    float2 oe;
    oe.x = me.x + si * mi.x + st * mt.x;
    oe.y = me.y + si * mi.y + st * mt.y;

    size_t slot = (size_t)i * EMBED + doff;
    size_t grp  = (size_t)BATCH * EMBED;
    *(float2*)(out + (size_t)g * grp + slot)       = oe;
    *(float2*)(out + (size_t)(3 + g) * grp + slot) = mi;
    *(float2*)(out + (size_t)(6 + g) * grp + slot) = mt;
}

// ---------------- launch ------------------------------------------------------
extern "C" void kernel_launch(void* const* d_in, const int* in_sizes, int n_in,
                              void* d_out, int out_size) {
    const int*   uidx   = (const int*)  d_in[0];
    const int*   pidx   = (const int*)  d_in[1];
    const int*   nidx   = (const int*)  d_in[2];
    const int*   arows  = (const int*)  d_in[3];
    const int*   acols  = (const int*)  d_in[4];
    const float* avals  = (const float*)d_in[5];
    const float* E0     = (const float*)d_in[6];
    const float* Wimg   = (const float*)d_in[7];
    const float* Bimg   = (const float*)d_in[8];
    const float* Wtxt   = (const float*)d_in[9];
    const float* Btxt   = (const float*)d_in[10];
    float* out = (float*)d_out;

    __half *F0, *F1, *F2;
    cudaGetSymbolAddress((void**)&F0, g_F0);
    cudaGetSymbolAddress((void**)&F1, g_F1);
    cudaGetSymbolAddress((void**)&F2, g_F2);

    // histogram + packed ranks (16 edges/thread for more ATOMG MLP)
    k_hist<<<NB_HIST, 256>>>(arows);

    // CSR offsets (two-pass)
    k_scan_p1<<<SCAN_NB, SCAN_T>>>();
    k_scan_p3<<<SCAN_NB, SCAN_T>>>();

    // striped scatter (4 edges/thread, 1:9) + feature init
    k_scatter_init<<<SI_GRID, 256>>>(arows, acols, avals, E0, Wimg, Wtxt);

    // layer 1 (dense) + needflag marker; layer 2 filtered
    k_spmm_mark<<<SPMM_BLOCKS + MARK_BLOCKS, 256>>>(F0, F1, Bimg, Btxt, uidx, pidx, nidx);
    k_spmm_filt<<<SPMM_BLOCKS, 256>>>(F1, F2, Bimg, Btxt);

    // final: on-the-fly layer 3 + sum/mean/normalize/gather (+ scratch resets)
    k_final<<<FIN_BLOCKS + ZERO_BLOCKS, 256>>>(uidx, pidx, nidx, Bimg, Btxt, out);
}